// round 11
// baseline (speedup 1.0000x reference)
#include <cuda_runtime.h>
#include <cuda_fp16.h>
#include <cstdint>
#include <math.h>

// ---------------------------------------------------------------------------
#define M_TOK 32768      // B*S
#define NDIM  512        // E = O
#define DT_C  0.01f
#define NSTEPS 10

#define BM 64
#define BN 128
#define BK 32
#define NCHUNK 16        // 512/32
#define NTHR 128         // 4 warps, warp tile 32x64
#define NSTAGE 4
#define NTILES ((M_TOK / BM) * (NDIM / BN))   // 512*4 = 2048
#define NPERS 304                              // 152 SMs x 2 resident CTAs

// smem: rows of 80B (64B data + 16B pad -> conflict-free ldmatrix)
#define ROWB 80
#define TILE_A_B (64 * ROWB)               // 5120
#define TILE_B_B (128 * ROWB)              // 10240
#define OFF_A  0
#define OFF_B  TILE_A_B
#define STAGE_BYTES (TILE_A_B + TILE_B_B)  // 15360
#define SM_CTRL 4608                       // 64 + bias[512] + fm[512]
#define GEMM_SMEM (SM_CTRL + NSTAGE * STAGE_BYTES)   // 66048; x2 CTAs = 132KB

// ---------------------------------------------------------------------------
// Global scratch (allocation-free rule)
// ---------------------------------------------------------------------------
__device__ __half g_act_a[M_TOK*NDIM];   // activations ping
__device__ __half g_act_b[M_TOK*NDIM];   // activations pong
__device__ float  g_ph[M_TOK*NDIM];      // fp32 phases for Kuramoto
__device__ __half g_w[4*NDIM*NDIM];      // transposed fp16 weights

// ---------------------------------------------------------------------------
// PTX helpers (sm_80-era only)
// ---------------------------------------------------------------------------
static __device__ __forceinline__ uint32_t smem_u32(const void* p) {
    uint32_t a;
    asm("{ .reg .u64 t; cvta.to.shared.u64 t, %1; cvt.u32.u64 %0, t; }" : "=r"(a) : "l"(p));
    return a;
}
static __device__ __forceinline__ void cp16(uint32_t dst, const void* src) {
    asm volatile("cp.async.cg.shared.global [%0], [%1], 16;" :: "r"(dst), "l"(src));
}
#define CP_COMMIT() asm volatile("cp.async.commit_group;" ::: "memory")
#define CP_WAIT(n)  asm volatile("cp.async.wait_group %0;" :: "n"(n) : "memory")

#define LDSM4(r, addr) \
    asm volatile("ldmatrix.sync.aligned.m8n8.x4.shared.b16 {%0,%1,%2,%3}, [%4];" \
        : "=r"((r)[0]), "=r"((r)[1]), "=r"((r)[2]), "=r"((r)[3]) : "r"(addr))

static __device__ __forceinline__ void mma16816(float* c, const uint32_t* a,
                                                const uint32_t b0, const uint32_t b1) {
    asm volatile("mma.sync.aligned.m16n8k16.row.col.f32.f16.f16.f32 "
        "{%0,%1,%2,%3}, {%4,%5,%6,%7}, {%8,%9}, {%0,%1,%2,%3};"
        : "+f"(c[0]), "+f"(c[1]), "+f"(c[2]), "+f"(c[3])
        : "r"(a[0]), "r"(a[1]), "r"(a[2]), "r"(a[3]), "r"(b0), "r"(b1));
}

// fast tanh via MUFU: 1 - 2/(exp(2x)+1); saturates correctly at +-inf
static __device__ __forceinline__ float ftanh(float x) {
    float e, r;
    const float u = x * 2.8853900817779268f;   // 2*log2(e)
    asm("ex2.approx.f32 %0, %1;" : "=f"(e) : "f"(u));
    asm("rcp.approx.f32 %0, %1;" : "=f"(r) : "f"(e + 1.0f));
    return fmaf(-2.0f, r, 1.0f);
}

// ---------------------------------------------------------------------------
// Load one K-chunk: A 64x32 fp16 + B 128x32 fp16. 6 cp16/thread (128 thr).
// ---------------------------------------------------------------------------
static __device__ __forceinline__ void load_chunk(
    uint32_t stage,
    const __half* __restrict__ A, const __half* __restrict__ B,
    int m0, int n0, int kc0, int tid)
{
#pragma unroll
    for (int i = 0; i < 2; i++) {
        const int t   = tid + i * NTHR;      // 0..255
        const int row = t >> 2;              // 0..63
        const int q   = t & 3;
        cp16(stage + OFF_A + (uint32_t)(row * ROWB + q * 16),
             A + (size_t)(m0 + row) * NDIM + kc0 + q * 8);
    }
#pragma unroll
    for (int i = 0; i < 4; i++) {
        const int t   = tid + i * NTHR;      // 0..511
        const int row = t >> 2;              // 0..127
        const int q   = t & 3;
        cp16(stage + OFF_B + (uint32_t)(row * ROWB + q * 16),
             B + (size_t)(n0 + row) * NDIM + kc0 + q * 8);
    }
    CP_COMMIT();
}

// ---------------------------------------------------------------------------
// Persistent fp16 GEMM: C[M,N] = act(A @ B^T + bias)
// CTA 64x128, 4 warps of 32x64, 4-stage cp.async ring continuous across tiles.
// 2048 tiles / 304 CTAs -> <=7 tiles each (3.9% tail vs 16% at 128x128).
// EPI: 0 -> fp32 outF; 1 -> tanh fp16 outH; 2 -> relu fp16 outH;
//      3 -> final [m,n,4] {v, im, im, im}, im = noise*sin(alpha*n)
// ---------------------------------------------------------------------------
template<int EPI>
__global__ void __launch_bounds__(NTHR, 2)
gemm_f16(const __half* __restrict__ A, const __half* __restrict__ B,
         const float* __restrict__ bias,
         __half* __restrict__ outH, float* __restrict__ outF,
         const float* __restrict__ noise, const float* __restrict__ alpha_p)
{
    extern __shared__ char smem[];
    const uint32_t sb = smem_u32(smem);
    const int tid  = threadIdx.x;
    const int wid  = tid >> 5;
    const int lane = tid & 31;

    const int wm = wid & 1;        // 2 warps along M (32 rows each)
    const int wn = wid >> 1;       // 2 warps along N (64 cols each)

    // full-width bias / fractal tables (tile-invariant)
    float* bias_s = (float*)(smem + 64);      // 512 floats
    float* fm_s   = (float*)(smem + 2112);    // 512 floats
    {
        const float alpha = (EPI == 3) ? *alpha_p : 0.f;
#pragma unroll
        for (int i = tid; i < NDIM; i += NTHR) {
            bias_s[i] = bias[i];
            if (EPI == 3) fm_s[i] = sinf(alpha * (float)i);
        }
    }

    int t  = blockIdx.x;
    int m0 = (t >> 2) * BM;
    int n0 = (t & 3) * BN;

    // prologue: 3 chunk-loads of first tile in flight
    load_chunk(sb + SM_CTRL + 0 * STAGE_BYTES, A, B, m0, n0, 0 * BK, tid);
    load_chunk(sb + SM_CTRL + 1 * STAGE_BYTES, A, B, m0, n0, 1 * BK, tid);
    load_chunk(sb + SM_CTRL + 2 * STAGE_BYTES, A, B, m0, n0, 2 * BK, tid);

    const int g  = lane >> 3;
    const int lr = lane & 7;
    const uint32_t offA = (uint32_t)((wm * 32 + (g & 1) * 8 + lr) * ROWB + (g >> 1) * 16);
    const uint32_t offB = (uint32_t)((wn * 64 + (g >> 1) * 8 + lr) * ROWB + (g & 1) * 16);

    while (true) {
        const int tn  = t + NPERS;
        const bool has_next = (tn < NTILES);
        const int m0n = (tn >> 2) * BM;
        const int n0n = (tn & 3) * BN;

        float acc[2][8][4];
#pragma unroll
        for (int mt = 0; mt < 2; mt++)
#pragma unroll
            for (int nt = 0; nt < 8; nt++)
#pragma unroll
                for (int r = 0; r < 4; r++) acc[mt][nt][r] = 0.f;

#pragma unroll 1
        for (int c = 0; c < NCHUNK; c++) {
            CP_WAIT(2);             // chunk c landed (c+1, c+2 pending)
            __syncthreads();        // all warps done with chunk c-1

            const int cc = c + 3;   // refill the slot chunk c-1 vacated
            if (cc < NCHUNK)
                load_chunk(sb + SM_CTRL + (cc & 3) * STAGE_BYTES,
                           A, B, m0, n0, cc * BK, tid);
            else if (has_next)
                load_chunk(sb + SM_CTRL + (cc & 3) * STAGE_BYTES,
                           A, B, m0n, n0n, (cc - NCHUNK) * BK, tid);
            else
                CP_COMMIT();        // empty group keeps accounting exact

            const uint32_t stage = sb + SM_CTRL + (c & 3) * STAGE_BYTES;
#pragma unroll
            for (int ks = 0; ks < 2; ks++) {
                uint32_t a[2][4], b[4][4];
#pragma unroll
                for (int mt = 0; mt < 2; mt++)
                    LDSM4(a[mt], stage + OFF_A + offA + mt * (16 * ROWB) + ks * 32);
#pragma unroll
                for (int bt = 0; bt < 4; bt++)
                    LDSM4(b[bt], stage + OFF_B + offB + bt * (16 * ROWB) + ks * 32);
#pragma unroll
                for (int mt = 0; mt < 2; mt++)
#pragma unroll
                    for (int nt = 0; nt < 8; nt++) {
                        const int bt = nt >> 1, sel = (nt & 1) * 2;
                        mma16816(acc[mt][nt], a[mt], b[bt][sel], b[bt][sel + 1]);
                    }
            }
        }

        // ---- epilogue: direct register -> global (overlaps next tile's loads)
        const int rbase = m0 + wm * 32 + (lane >> 2);
        const int cbase = n0 + wn * 64 + (lane & 3) * 2;
#pragma unroll
        for (int mt = 0; mt < 2; mt++)
#pragma unroll
            for (int nt = 0; nt < 8; nt++) {
                const int col = cbase + nt * 8;
#pragma unroll
                for (int h = 0; h < 2; h++) {
                    const int row = rbase + mt * 16 + h * 8;
                    float v0 = acc[mt][nt][h * 2 + 0] + bias_s[col + 0];
                    float v1 = acc[mt][nt][h * 2 + 1] + bias_s[col + 1];
                    const size_t e = (size_t)row * NDIM + col;
                    if (EPI == 1) {
                        *(__half2*)(outH + e) = __floats2half2_rn(ftanh(v0), ftanh(v1));
                    } else if (EPI == 2) {
                        *(__half2*)(outH + e) =
                            __floats2half2_rn(fmaxf(v0, 0.f), fmaxf(v1, 0.f));
                    } else if (EPI == 0) {
                        *(float2*)(outF + e) = make_float2(v0, v1);
                    } else {
                        const float2 nz = *(const float2*)(noise + e);
                        const float im0 = nz.x * fm_s[col + 0];
                        const float im1 = nz.y * fm_s[col + 1];
                        *(float4*)(outF + e * 4)       = make_float4(v0, im0, im0, im0);
                        *(float4*)(outF + (e + 1) * 4) = make_float4(v1, im1, im1, im1);
                    }
                }
            }

        if (!has_next) break;
        t = tn; m0 = m0n; n0 = n0n;
    }
}

// ---------------------------------------------------------------------------
// fp32 -> fp16 (for x)
// ---------------------------------------------------------------------------
__global__ void __launch_bounds__(256)
conv_f16(const float* __restrict__ x, __half* __restrict__ o)
{
    const int n4 = M_TOK * NDIM / 4;
    for (int i = blockIdx.x * blockDim.x + threadIdx.x; i < n4; i += gridDim.x * blockDim.x) {
        const float4 v = *(const float4*)(x + i * 4);
        __half2* O = (__half2*)(o + i * 4);
        O[0] = __floats2half2_rn(v.x, v.y);
        O[1] = __floats2half2_rn(v.z, v.w);
    }
}

// ---------------------------------------------------------------------------
// Weight prep (all 4 weights in one launch): Wt[n,k] = W[k,n] as fp16
// ---------------------------------------------------------------------------
__global__ void __launch_bounds__(256)
wprep4(const float* __restrict__ W1, const float* __restrict__ W2,
       const float* __restrict__ F1, const float* __restrict__ F2,
       __half* __restrict__ T)
{
    const float* W = (blockIdx.z == 0) ? W1 : (blockIdx.z == 1) ? W2
                   : (blockIdx.z == 2) ? F1 : F2;
    __half* Tz = T + (size_t)blockIdx.z * NDIM * NDIM;

    __shared__ float tile[32][33];
    const int bx = blockIdx.x * 32, by = blockIdx.y * 32;
    const int tx = threadIdx.x & 31, ty = threadIdx.x >> 5;  // 32 x 8
#pragma unroll
    for (int r = 0; r < 32; r += 8)
        tile[ty + r][tx] = W[(size_t)(by + ty + r) * NDIM + bx + tx];
    __syncthreads();
#pragma unroll
    for (int r = 0; r < 32; r += 8)
        Tz[(size_t)(bx + ty + r) * NDIM + by + tx] = __float2half_rn(tile[tx][ty + r]);
}

// ---------------------------------------------------------------------------
// Kuramoto: 10 steps (rotation trick), emits fp16 phases
// ---------------------------------------------------------------------------
__global__ void __launch_bounds__(256)
kuramoto_kernel(const float* __restrict__ P, const float* __restrict__ omega,
                const float* __restrict__ Kp, __half* __restrict__ outH)
{
    const int gwarp = (blockIdx.x * blockDim.x + threadIdx.x) >> 5;
    const int lane  = threadIdx.x & 31;
    if (gwarp >= M_TOK) return;

    const float* ph = P + (size_t)gwarp * NDIM;
    const float Kv = *Kp;
    const float a_scale = DT_C * Kv * (1.0f / (float)NDIM);

    float p[16], s[16], c[16], w[16];
#pragma unroll
    for (int i = 0; i < 16; i++) {
        const int e = lane + 32 * i;
        p[i] = ph[e];
        w[i] = DT_C * omega[e];
        __sincosf(p[i], &s[i], &c[i]);   // MUFU; |p| ~ O(3), err ~1e-6
    }
#pragma unroll 1
    for (int step = 0; step < NSTEPS; step++) {
        float part = 0.f;
#pragma unroll
        for (int i = 0; i < 16; i++) part += s[i];
#pragma unroll
        for (int off = 16; off > 0; off >>= 1)
            part += __shfl_xor_sync(0xFFFFFFFFu, part, off);
        const float a = a_scale * part;
#pragma unroll
        for (int i = 0; i < 16; i++) {
            const float d  = fmaf(a, c[i], w[i]);
            p[i] += d;
            const float cd = fmaf(-0.5f * d, d, 1.0f);
            const float sn = fmaf(c[i],  d, s[i] * cd);
            const float cn = fmaf(-s[i], d, c[i] * cd);
            s[i] = sn; c[i] = cn;
        }
    }
    const size_t base = (size_t)gwarp * NDIM;
#pragma unroll
    for (int i = 0; i < 16; i++)
        outH[base + lane + 32 * i] = __float2half_rn(p[i]);
}

// ---------------------------------------------------------------------------
extern "C" void kernel_launch(void* const* d_in, const int* in_sizes, int n_in,
                              void* d_out, int out_size)
{
    const float* x      = (const float*)d_in[0];
    const float* W1     = (const float*)d_in[1];
    const float* b1     = (const float*)d_in[2];
    const float* W2     = (const float*)d_in[3];
    const float* b2     = (const float*)d_in[4];
    const float* omega  = (const float*)d_in[5];
    const float* Kp     = (const float*)d_in[6];
    const float* alphap = (const float*)d_in[7];
    const float* F1     = (const float*)d_in[8];
    const float* c1     = (const float*)d_in[9];
    const float* F2     = (const float*)d_in[10];
    const float* c2     = (const float*)d_in[11];
    const float* noise  = (const float*)d_in[12];
    float* out = (float*)d_out;

    __half *actA, *actB, *wT;
    float* phb;
    cudaGetSymbolAddress((void**)&actA, g_act_a);
    cudaGetSymbolAddress((void**)&actB, g_act_b);
    cudaGetSymbolAddress((void**)&wT,   g_w);
    cudaGetSymbolAddress((void**)&phb,  g_ph);

    cudaFuncSetAttribute(gemm_f16<0>, cudaFuncAttributeMaxDynamicSharedMemorySize, GEMM_SMEM);
    cudaFuncSetAttribute(gemm_f16<1>, cudaFuncAttributeMaxDynamicSharedMemorySize, GEMM_SMEM);
    cudaFuncSetAttribute(gemm_f16<2>, cudaFuncAttributeMaxDynamicSharedMemorySize, GEMM_SMEM);
    cudaFuncSetAttribute(gemm_f16<3>, cudaFuncAttributeMaxDynamicSharedMemorySize, GEMM_SMEM);

    const size_t WSZ = (size_t)NDIM * NDIM;
    wprep4<<<dim3(16, 16, 4), 256>>>(W1, W2, F1, F2, wT);
    conv_f16<<<2048, 256>>>(x, actA);

    // phases = tanh(x @ W1 + b1) -> fp16
    gemm_f16<1><<<NPERS, NTHR, GEMM_SMEM>>>(actA, wT + 0*WSZ,
                                            b1, actB, nullptr, nullptr, nullptr);
    // phases = phases @ W2 + b2 -> fp32
    gemm_f16<0><<<NPERS, NTHR, GEMM_SMEM>>>(actB, wT + 1*WSZ,
                                            b2, nullptr, phb, nullptr, nullptr);
    // Kuramoto -> fp16 phases
    kuramoto_kernel<<<M_TOK / 8, 256>>>(phb, omega, Kp, actA);
    // h = relu(phases @ F1 + c1) -> fp16
    gemm_f16<2><<<NPERS, NTHR, GEMM_SMEM>>>(actA, wT + 2*WSZ,
                                            c1, actB, nullptr, nullptr, nullptr);
    // out = expand(h @ F2 + c2, noise)
    gemm_f16<3><<<NPERS, NTHR, GEMM_SMEM>>>(actB, wT + 3*WSZ,
                                            c2, nullptr, out, noise, alphap);
}